// round 16
// baseline (speedup 1.0000x reference)
#include <cuda_runtime.h>
#include <cuda_fp16.h>
#include <cstdint>
#include <cstddef>

// Problem dims
#define VN 128
#define HN 512
#define BN 512
#define SN 256

// Static scratch (module-load allocated; no runtime allocation)
// h is stored fp16, perm32-permuted within each 32-k chunk.
__device__ __half g_hs_f[(size_t)(SN + 1) * BN * HN];
__device__ __half g_hs_b[(size_t)(SN + 1) * BN * HN];
__device__ float  g_c[2 * BN * HN];                    // cell state (plain layout, fp32)
// Pre-packed fp16 weights, perm32'd k: [dir][n = j*4+gate][k'], k<512 Wh, k>=512 Wx
__device__ __half g_w[(size_t)2 * 2048 * 640];
__device__ __half g_wfc[(size_t)VN * 1024];            // perm32'd [v][k']

// perm32: slot s = q*8 + j  <->  k = (j>>2)*16 + ((j>>1)&1)*8 + (j&1) + 2*q
__device__ __host__ __forceinline__ int slot2k(int s) {
    int q = s >> 3, j = s & 7;
    return (j >> 2) * 16 + ((j >> 1) & 1) * 8 + (j & 1) + 2 * q;
}
__device__ __forceinline__ int k2slot(int k) {
    int q = (k & 7) >> 1, b1 = k & 1, b2 = (k >> 3) & 1, b4 = (k >> 4) & 1;
    return q * 8 + b4 * 4 + b2 * 2 + b1;
}

__device__ __forceinline__ void mma_f16(float* d, const unsigned* a, const unsigned* b) {
    asm volatile(
        "mma.sync.aligned.m16n8k16.row.col.f32.f16.f16.f32 "
        "{%0,%1,%2,%3}, {%4,%5,%6,%7}, {%8,%9}, {%0,%1,%2,%3};\n"
        : "+f"(d[0]), "+f"(d[1]), "+f"(d[2]), "+f"(d[3])
        : "r"(a[0]), "r"(a[1]), "r"(a[2]), "r"(a[3]),
          "r"(b[0]), "r"(b[1]));
}

__device__ __forceinline__ float sigmf(float x) { return 1.0f / (1.0f + expf(-x)); }

// Build one-hot A fragment quarter: two fp16 values packed per 32-bit word.
__device__ __forceinline__ uint4 mkoh(int xv, int kb) {
    uint4 r;
    r.x = (xv == kb      ? 0x3C00u : 0u) | (xv == kb + 1  ? 0x3C000000u : 0u);
    r.y = (xv == kb + 8  ? 0x3C00u : 0u) | (xv == kb + 9  ? 0x3C000000u : 0u);
    r.z = (xv == kb + 16 ? 0x3C00u : 0u) | (xv == kb + 17 ? 0x3C000000u : 0u);
    r.w = (xv == kb + 24 ? 0x3C00u : 0u) | (xv == kb + 25 ? 0x3C000000u : 0u);
    return r;
}

__global__ void init_kernel() {
    int i = blockIdx.x * blockDim.x + threadIdx.x;
    if (i < BN * HN) {
        g_hs_f[i] = __ushort_as_half(0);
        g_hs_b[i] = __ushort_as_half(0);
    }
    if (i < 2 * BN * HN) g_c[i] = 0.f;
}

// Pack [Wh | Wx] -> fp16, n = j*4+gate, k' = perm32 within 32-chunks.
__global__ void pack_w_kernel(const float* __restrict__ Wh_f, const float* __restrict__ Wx_f,
                              const float* __restrict__ Wh_b, const float* __restrict__ Wx_b) {
    size_t i = (size_t)blockIdx.x * blockDim.x + threadIdx.x;
    const size_t total = (size_t)2 * 2048 * 640;
    if (i >= total) return;
    int kp = (int)(i % 640);
    int n = (int)((i / 640) % 2048);
    int d = (int)(i / ((size_t)640 * 2048));
    int k = (kp & ~31) + slot2k(kp & 31);
    int j = n >> 2, gate = n & 3;
    const float* Wh = d ? Wh_b : Wh_f;
    const float* Wx = d ? Wx_b : Wx_f;
    float v = (k < 512) ? Wh[((size_t)gate * HN + j) * HN + k]
                        : Wx[((size_t)gate * HN + j) * VN + (k - 512)];
    g_w[i] = __float2half_rn(v);
}

__global__ void pack_wfc_kernel(const float* __restrict__ Wfc) {
    int i = blockIdx.x * blockDim.x + threadIdx.x;
    if (i >= VN * 1024) return;
    int kp = i & 1023, v = i >> 10;
    int k = (kp & ~31) + slot2k(kp & 31);
    g_wfc[i] = __float2half_rn(Wfc[v * 1024 + k]);
}

// ============================================================================
// step_kernel: one recurrence step, both directions (blockIdx.z).
// CTA tile 64 batch x 128 gemm cols (32 neurons x 4 gates), K=640 fp16.
// 256 threads = 8 warps (2m x 4n), warp tile 32x32, MMA m16n8k16.
// NO SMEM staging, NO mainloop barriers: A fragments loaded DIRECTLY from
// perm32'd global h via LDG.128; one-hot chunks synthesized in registers;
// B fragments direct LDG.128 from pre-packed g_w. 2-stage register pipeline.
// ============================================================================
__global__ __launch_bounds__(256, 2) void step_kernel(
    int t, const int* __restrict__ x,
    const float* __restrict__ bx_f, const float* __restrict__ bh_f,
    const float* __restrict__ bx_b, const float* __restrict__ bh_b) {
    __shared__ __align__(16) float bsum[128];

    const int tid = threadIdx.x;
    const int d = blockIdx.z;
    const int b0 = blockIdx.x * 64;
    const int j0 = blockIdx.y * 32;   // first neuron of this CTA
    const int t_eff = d ? (SN - 1 - t) : t;

    const float* __restrict__ bxp = d ? bx_b : bx_f;
    const float* __restrict__ bhp = d ? bh_b : bh_f;
    __half* hs = d ? g_hs_b : g_hs_f;
    float* cst = g_c + (size_t)d * BN * HN;
    const __half* hprev = hs + (size_t)t * BN * HN;
    __half* hout = hs + (size_t)(t + 1) * BN * HN;

    if (tid < 128) {   // per-col bias sums (col n = jj*4+gate)
        int jj = tid >> 2, gate = tid & 3, j = j0 + jj;
        bsum[tid] = bxp[gate * HN + j] + bhp[gate * HN + j];
    }
    __syncthreads();   // the only block barrier

    const int w = tid >> 5, lane = tid & 31;
    const int wm = w >> 2, wn = w & 3;               // 2x4 warp grid, warp tile 32x32
    const int gr = lane >> 2, q = lane & 3;

    // A: this lane's fragment rows are r0, r0+8, r0+16, r0+24 (tm x {lo,hi})
    const int r0 = b0 + wm * 32 + gr;
    const __half* aPtr = hprev + (size_t)r0 * HN + q * 8;
    // token values for one-hot chunks (rows r0, r0+8, r0+16, r0+24)
    const int xv0 = x[(r0)      * SN + t_eff];
    const int xv1 = x[(r0 + 8)  * SN + t_eff];
    const int xv2 = x[(r0 + 16) * SN + t_eff];
    const int xv3 = x[(r0 + 24) * SN + t_eff];

    const __half* bPtr = g_w + ((size_t)d * 2048 + (size_t)j0 * 4 + wn * 32 + gr) * 640 + q * 8;

    float acc[2][4][4];
#pragma unroll
    for (int i = 0; i < 2; i++)
#pragma unroll
        for (int jx = 0; jx < 4; jx++)
#pragma unroll
            for (int kx = 0; kx < 4; kx++) acc[i][jx][kx] = 0.f;

    // register pipeline: stage = {A frags [4], B frags [4]}
    uint4 aF[2][4], bF[2][4];

    auto loadA = [&](int ch, int st) {
        if (ch < 16) {
            const __half* p = aPtr + ch * 32;
            aF[st][0] = *(const uint4*)(p);
            aF[st][1] = *(const uint4*)(p + 8 * HN);
            aF[st][2] = *(const uint4*)(p + 16 * HN);
            aF[st][3] = *(const uint4*)(p + 24 * HN);
        } else {
            int kb = (ch - 16) * 32 + 2 * q;
            aF[st][0] = mkoh(xv0, kb);
            aF[st][1] = mkoh(xv1, kb);
            aF[st][2] = mkoh(xv2, kb);
            aF[st][3] = mkoh(xv3, kb);
        }
    };
    auto loadB = [&](int ch, int st) {
#pragma unroll
        for (int tn = 0; tn < 4; tn++)
            bF[st][tn] = *(const uint4*)(bPtr + (size_t)tn * 8 * 640 + ch * 32);
    };
    auto compute = [&](int st) {
#pragma unroll
        for (int tm = 0; tm < 2; tm++) {
            uint4 A0 = aF[st][tm * 2];
            uint4 A1 = aF[st][tm * 2 + 1];
            unsigned af0[4] = {A0.x, A1.x, A0.y, A1.y};
            unsigned af1[4] = {A0.z, A1.z, A0.w, A1.w};
#pragma unroll
            for (int tn = 0; tn < 4; tn++) {
                unsigned bk0[2] = {bF[st][tn].x, bF[st][tn].y};
                unsigned bk1[2] = {bF[st][tn].z, bF[st][tn].w};
                mma_f16(acc[tm][tn], af0, bk0);
                mma_f16(acc[tm][tn], af1, bk1);
            }
        }
    };

    loadA(0, 0);
    loadB(0, 0);
#pragma unroll 2
    for (int ch = 0; ch < 20; ch++) {
        const int p = ch & 1;
        if (ch + 1 < 20) {
            loadA(ch + 1, p ^ 1);
            loadB(ch + 1, p ^ 1);
        }
        compute(p);
    }

    // Epilogue: lane pair (l, l^1) exchanges to gather all 4 gates of a cell.
#pragma unroll
    for (int tm = 0; tm < 2; tm++) {
        int rbase = b0 + wm * 32 + tm * 16 + gr;
#pragma unroll
        for (int tn = 0; tn < 4; tn++) {
            float c0 = acc[tm][tn][0], c1 = acc[tm][tn][1];
            float c2 = acc[tm][tn][2], c3 = acc[tm][tn][3];
            float e0 = __shfl_xor_sync(0xffffffffu, c0, 1);
            float e1 = __shfl_xor_sync(0xffffffffu, c1, 1);
            float e2 = __shfl_xor_sync(0xffffffffu, c2, 1);
            float e3 = __shfl_xor_sync(0xffffffffu, c3, 1);
            float iv, fv, ov, gv;
            int brow;
            if ((q & 1) == 0) { iv = c0; fv = c1; ov = e0; gv = e1; brow = rbase; }
            else              { iv = e2; fv = e3; ov = c2; gv = c3; brow = rbase + 8; }
            int jj4 = wn * 32 + tn * 8 + (q >> 1) * 4;
            float4 bs = *(const float4*)&bsum[jj4];
            float gi = sigmf(iv + bs.x);
            float gf = sigmf(fv + bs.y);
            float go = sigmf(ov + bs.z);
            float gg = tanhf(gv + bs.w);
            int jg = j0 + (jj4 >> 2);
            int kp = (jg & ~31) + k2slot(jg & 31);   // store h perm32'd
            size_t ci = (size_t)brow * HN + jg;
            float cn = gf * cst[ci] + gi * gg;
            cst[ci] = cn;
            hout[(size_t)brow * HN + kp] = __float2half_rn(go * tanhf(cn));
        }
    }
}

// ============================================================================
// fc_kernel: y[b,s,v] = [hf(s)|hb(s)] . Wfc[v,:] + bfc[v]. K=1024 fp16,
// 32 chunks of 32. CTA 128 rows x 128 cols, 512 threads = 16 warps (4m x 4n),
// warp tile 32x32 (tm=2 m16 tiles). A via smem (perm32 h), B direct LDG.
// ============================================================================
__global__ __launch_bounds__(512, 1) void fc_kernel(const float* __restrict__ bfc,
                                                    float* __restrict__ y) {
    __shared__ __align__(16) __half As[2][2][128 * 32];
    __shared__ float bsh[128];

    const int tid = threadIdx.x;
    const int s = blockIdx.x >> 2;
    const int b0r = (blockIdx.x & 3) * 128;

    const __half* Af = g_hs_f + (size_t)(s + 1) * BN * HN;
    const __half* Ab = g_hs_b + (size_t)(SN - s) * BN * HN;

    if (tid < 128) bsh[tid] = bfc[tid];

    const int lrow = tid >> 2, lseg = tid & 3;       // 8 halfs/thread/chunk
    const int w = tid >> 5, lane = tid & 31;
    const int wm = w >> 2, wn = w & 3;               // 4x4 warp grid, warp tile 32x32
    const int gr = lane >> 2, q = lane & 3;
    const int swz = (gr >> 1) & 3;
    const int stsOff = lrow * 32 + 8 * (lseg ^ ((lrow >> 1) & 3));
    const int aOffBase = wm * 1024 + gr * 32 + 8 * (q ^ swz);   // warp covers 32 rows

    const __half* afRow = Af + (size_t)(b0r + lrow) * HN;
    const __half* abRow = Ab + (size_t)(b0r + lrow) * HN;
    const __half* bPtr = g_wfc + (size_t)(wn * 32 + gr) * 1024 + q * 8;

    float acc[2][4][4];
#pragma unroll
    for (int i = 0; i < 2; i++)
#pragma unroll
        for (int jx = 0; jx < 4; jx++)
#pragma unroll
            for (int kx = 0; kx < 4; kx++) acc[i][jx][kx] = 0.f;

    uint4 bF[2][4], rA0, rA1;

    auto loadAFC = [&](int ch, uint4& dst) {
        const __half* src = (ch < 16) ? (afRow + ch * 32) : (abRow + (ch - 16) * 32);
        dst = *(const uint4*)(src + lseg * 8);
    };
    auto loadBFC = [&](int ch, int buf) {
#pragma unroll
        for (int tn = 0; tn < 4; tn++)
            bF[buf][tn] = *(const uint4*)(bPtr + (size_t)tn * 8 * 1024 + ch * 32);
    };
    auto compFC = [&](const __half* S, int bb) {
#pragma unroll
        for (int tm = 0; tm < 2; tm++) {
            const __half* base = S + tm * 512 + aOffBase;
            uint4 A0 = *(const uint4*)(base);
            uint4 A1 = *(const uint4*)(base + 256);
            unsigned af0[4] = {A0.x, A1.x, A0.y, A1.y};
            unsigned af1[4] = {A0.z, A1.z, A0.w, A1.w};
#pragma unroll
            for (int tn = 0; tn < 4; tn++) {
                unsigned bk0[2] = {bF[bb][tn].x, bF[bb][tn].y};
                unsigned bk1[2] = {bF[bb][tn].z, bF[bb][tn].w};
                mma_f16(acc[tm][tn], af0, bk0);
                mma_f16(acc[tm][tn], af1, bk1);
            }
        }
    };

    loadAFC(0, rA0);
    loadAFC(1, rA1);
    loadBFC(0, 0);
    for (int kc = 0; kc < 32; kc += 2) {
        const int p = (kc >> 1) & 1;
        *(uint4*)(&As[p][0][stsOff]) = rA0;
        *(uint4*)(&As[p][1][stsOff]) = rA1;
        loadBFC(kc + 1, 1);
        if (kc + 2 < 32) { loadAFC(kc + 2, rA0); loadAFC(kc + 3, rA1); }
        __syncthreads();
        compFC(As[p][0], 0);
        if (kc + 2 < 32) loadBFC(kc + 2, 0);
        compFC(As[p][1], 1);
    }

#pragma unroll
    for (int tm = 0; tm < 2; tm++) {
        int b = b0r + wm * 32 + tm * 16 + gr;
#pragma unroll
        for (int tn = 0; tn < 4; tn++) {
            int n0 = wn * 32 + tn * 8 + 2 * q;
            float2 w0 = make_float2(acc[tm][tn][0] + bsh[n0], acc[tm][tn][1] + bsh[n0 + 1]);
            *(float2*)(y + ((size_t)b * SN + s) * VN + n0) = w0;
            float2 w1 = make_float2(acc[tm][tn][2] + bsh[n0], acc[tm][tn][3] + bsh[n0 + 1]);
            *(float2*)(y + ((size_t)(b + 8) * SN + s) * VN + n0) = w1;
        }
    }
}

extern "C" void kernel_launch(void* const* d_in, const int* in_sizes, int n_in,
                              void* d_out, int out_size) {
    const int*   x    = (const int*)d_in[0];
    const float* Wx_f = (const float*)d_in[1];
    const float* Wh_f = (const float*)d_in[2];
    const float* bx_f = (const float*)d_in[3];
    const float* bh_f = (const float*)d_in[4];
    const float* Wx_b = (const float*)d_in[5];
    const float* Wh_b = (const float*)d_in[6];
    const float* bx_b = (const float*)d_in[7];
    const float* bh_b = (const float*)d_in[8];
    const float* Wfc  = (const float*)d_in[9];
    const float* bfc  = (const float*)d_in[10];
    float* y = (float*)d_out;

    init_kernel<<<2048, 256>>>();
    pack_w_kernel<<<(2 * 2048 * 640 + 255) / 256, 256>>>(Wh_f, Wx_f, Wh_b, Wx_b);
    pack_wfc_kernel<<<(VN * 1024 + 255) / 256, 256>>>(Wfc);

    // 256 sequential recurrence steps; both directions fused per launch.
    dim3 g(8, 16, 2);  // 8 batch tiles x 16 neuron tiles x 2 directions = 256 CTAs (2/SM)
    for (int t = 0; t < SN; t++)
        step_kernel<<<g, 256>>>(t, x, bx_f, bh_f, bx_b, bh_b);

    // final projection over all (s, b): 256 s x 4 batch tiles
    fc_kernel<<<1024, 512>>>(bfc, y);
}

// round 17
// speedup vs baseline: 1.4911x; 1.4911x over previous
#include <cuda_runtime.h>
#include <cuda_fp16.h>
#include <cstdint>
#include <cstddef>

// Problem dims
#define VN 128
#define HN 512
#define BN 512
#define SN 256

// Static scratch (module-load allocated; no runtime allocation)
// h is stored fp16, perm32-permuted within each 32-k chunk.
__device__ __half g_hs_f[(size_t)(SN + 1) * BN * HN];
__device__ __half g_hs_b[(size_t)(SN + 1) * BN * HN];
__device__ float  g_c[2 * BN * HN];                    // cell state (plain layout, fp32)
// Pre-packed fp16 weights, perm32'd k: [dir][n = j*4+gate][k'], k<512 Wh (Wx part unused now)
__device__ __half g_w[(size_t)2 * 2048 * 640];
__device__ __half g_wfc[(size_t)VN * 1024];            // perm32'd [v][k']
// Pre-packed input-gather table: [dir][v][n] = fp16(Wx[n,v] + bx[n] + bh[n]), n = j*4+gate
__device__ __half g_wxp[(size_t)2 * VN * 2048];

// perm32: slot s = q*8 + j  <->  k = (j>>2)*16 + ((j>>1)&1)*8 + (j&1) + 2*q
__device__ __host__ __forceinline__ int slot2k(int s) {
    int q = s >> 3, j = s & 7;
    return (j >> 2) * 16 + ((j >> 1) & 1) * 8 + (j & 1) + 2 * q;
}
__device__ __forceinline__ int k2slot(int k) {
    int q = (k & 7) >> 1, b1 = k & 1, b2 = (k >> 3) & 1, b4 = (k >> 4) & 1;
    return q * 8 + b4 * 4 + b2 * 2 + b1;
}

__device__ __forceinline__ void mma_f16(float* d, const unsigned* a, const unsigned* b) {
    asm volatile(
        "mma.sync.aligned.m16n8k16.row.col.f32.f16.f16.f32 "
        "{%0,%1,%2,%3}, {%4,%5,%6,%7}, {%8,%9}, {%0,%1,%2,%3};\n"
        : "+f"(d[0]), "+f"(d[1]), "+f"(d[2]), "+f"(d[3])
        : "r"(a[0]), "r"(a[1]), "r"(a[2]), "r"(a[3]),
          "r"(b[0]), "r"(b[1]));
}

__device__ __forceinline__ float sigmf(float x) { return 1.0f / (1.0f + expf(-x)); }

__global__ void init_kernel() {
    int i = blockIdx.x * blockDim.x + threadIdx.x;
    if (i < BN * HN) {
        g_hs_f[i] = __ushort_as_half(0);
        g_hs_b[i] = __ushort_as_half(0);
    }
    if (i < 2 * BN * HN) g_c[i] = 0.f;
}

// Pack [Wh | Wx] -> fp16, n = j*4+gate, k' = perm32 within 32-chunks.
__global__ void pack_w_kernel(const float* __restrict__ Wh_f, const float* __restrict__ Wx_f,
                              const float* __restrict__ Wh_b, const float* __restrict__ Wx_b) {
    size_t i = (size_t)blockIdx.x * blockDim.x + threadIdx.x;
    const size_t total = (size_t)2 * 2048 * 640;
    if (i >= total) return;
    int kp = (int)(i % 640);
    int n = (int)((i / 640) % 2048);
    int d = (int)(i / ((size_t)640 * 2048));
    int k = (kp & ~31) + slot2k(kp & 31);
    int j = n >> 2, gate = n & 3;
    const float* Wh = d ? Wh_b : Wh_f;
    const float* Wx = d ? Wx_b : Wx_f;
    float v = (k < 512) ? Wh[((size_t)gate * HN + j) * HN + k]
                        : Wx[((size_t)gate * HN + j) * VN + (k - 512)];
    g_w[i] = __float2half_rn(v);
}

__global__ void pack_wfc_kernel(const float* __restrict__ Wfc) {
    int i = blockIdx.x * blockDim.x + threadIdx.x;
    if (i >= VN * 1024) return;
    int kp = i & 1023, v = i >> 10;
    int k = (kp & ~31) + slot2k(kp & 31);
    g_wfc[i] = __float2half_rn(Wfc[v * 1024 + k]);
}

// Pack g_wxp[d][v][n] = fp16(Wx[n, v] + bx[n] + bh[n]),  n = j*4 + gate.
__global__ void pack_wxp_kernel(const float* __restrict__ Wx_f, const float* __restrict__ bx_f,
                                const float* __restrict__ bh_f,
                                const float* __restrict__ Wx_b, const float* __restrict__ bx_b,
                                const float* __restrict__ bh_b) {
    int i = blockIdx.x * blockDim.x + threadIdx.x;
    const int total = 2 * VN * 2048;
    if (i >= total) return;
    int n = i & 2047;
    int v = (i >> 11) & (VN - 1);
    int d = i >> 18;
    int j = n >> 2, gate = n & 3;
    const float* Wx = d ? Wx_b : Wx_f;
    const float* bx = d ? bx_b : bx_f;
    const float* bh = d ? bh_b : bh_f;
    float val = Wx[((size_t)gate * HN + j) * VN + v] + bx[gate * HN + j] + bh[gate * HN + j];
    g_wxp[i] = __float2half_rn(val);
}

// ============================================================================
// step_kernel: one recurrence step, both directions (blockIdx.z).
// CTA tile 64 batch x 128 gemm cols (32 neurons x 4 gates), K=512 fp16
// (input one-hot term pre-gathered into bsum2 via g_wxp -> no GEMM chunks).
// 256 threads = 8 warps (2m x 4n), warp tile 32x32, MMA m16n8k16.
// 16 chunks of K=32; pairs share one __syncthreads. A via smem (perm32 +
// row-swizzle, LDS.128 = full k32 fragment set). B direct LDG.128 from g_w.
// ============================================================================
__global__ __launch_bounds__(256, 2) void step_kernel(
    int t, const int* __restrict__ x) {
    __shared__ __align__(16) __half As[2][2][64 * 32];   // [buf][chunk-in-pair][...]
    __shared__ __align__(16) __half bsum2[64 * 128];     // per-(row, col) bias + wx gather

    const int tid = threadIdx.x;
    const int d = blockIdx.z;
    const int b0 = blockIdx.x * 64;
    const int j0 = blockIdx.y * 32;   // first neuron of this CTA
    const int t_eff = d ? (SN - 1 - t) : t;

    __half* hs = d ? g_hs_b : g_hs_f;
    float* cst = g_c + (size_t)d * BN * HN;
    const __half* hprev = hs + (size_t)t * BN * HN;
    __half* hout = hs + (size_t)(t + 1) * BN * HN;

    const int lrow = tid >> 2, lseg = tid & 3;       // A loader: 8 halfs/thread/chunk
    const int w = tid >> 5, lane = tid & 31;
    const int wm = w >> 2, wn = w & 3;               // 2x4 warp grid, warp tile 32x32
    const int gr = lane >> 2, q = lane & 3;
    const int swz = (gr >> 1) & 3;
    const int stsOff = lrow * 32 + 8 * (lseg ^ ((lrow >> 1) & 3));   // half units
    const int aOffBase = wm * 1024 + gr * 32 + 8 * (q ^ swz);        // +row*32 halfs

    // --- setup: gather per-(row,col) bias+wx into bsum2 (replaces one-hot chunks) ---
    {
        int xv = x[(b0 + lrow) * SN + t_eff];
        const uint4* src = (const uint4*)(g_wxp + ((size_t)d * VN + xv) * 2048 + j0 * 4);
        uint4* dst = (uint4*)(bsum2 + lrow * 128);
#pragma unroll
        for (int i = 0; i < 4; i++)
            dst[lseg * 4 + i] = src[lseg * 4 + i];
    }
    __syncthreads();

    const __half* aRow = hprev + (size_t)(b0 + lrow) * HN;
    const __half* bPtr = g_w + ((size_t)d * 2048 + (size_t)j0 * 4 + wn * 32 + gr) * 640 + q * 8;

    float acc[2][4][4];
#pragma unroll
    for (int i = 0; i < 2; i++)
#pragma unroll
        for (int jx = 0; jx < 4; jx++)
#pragma unroll
            for (int kx = 0; kx < 4; kx++) acc[i][jx][kx] = 0.f;

    uint4 bF[2][4], rA0, rA1;

    auto loadA = [&](int ch, uint4& dst) {
        dst = *(const uint4*)(aRow + ch * 32 + lseg * 8);
    };
    auto loadB = [&](int ch, int buf) {
#pragma unroll
        for (int tn = 0; tn < 4; tn++)
            bF[buf][tn] = *(const uint4*)(bPtr + (size_t)tn * 8 * 640 + ch * 32);
    };
    auto compute = [&](const __half* S, int bb) {
#pragma unroll
        for (int tm = 0; tm < 2; tm++) {
            const __half* base = S + tm * 512 + aOffBase;
            uint4 A0 = *(const uint4*)(base);
            uint4 A1 = *(const uint4*)(base + 256);
            unsigned af0[4] = {A0.x, A1.x, A0.y, A1.y};
            unsigned af1[4] = {A0.z, A1.z, A0.w, A1.w};
#pragma unroll
            for (int tn = 0; tn < 4; tn++) {
                unsigned bk0[2] = {bF[bb][tn].x, bF[bb][tn].y};
                unsigned bk1[2] = {bF[bb][tn].z, bF[bb][tn].w};
                mma_f16(acc[tm][tn], af0, bk0);
                mma_f16(acc[tm][tn], af1, bk1);
            }
        }
    };

    loadA(0, rA0);
    loadA(1, rA1);
    loadB(0, 0);
    for (int kc = 0; kc < 16; kc += 2) {
        const int p = (kc >> 1) & 1;
        *(uint4*)(&As[p][0][stsOff]) = rA0;
        *(uint4*)(&As[p][1][stsOff]) = rA1;
        loadB(kc + 1, 1);
        if (kc + 2 < 16) { loadA(kc + 2, rA0); loadA(kc + 3, rA1); }
        __syncthreads();
        compute(As[p][0], 0);
        if (kc + 2 < 16) loadB(kc + 2, 0);
        compute(As[p][1], 1);
    }

    // Epilogue: lane pair (l, l^1) exchanges to gather all 4 gates of a cell.
#pragma unroll
    for (int tm = 0; tm < 2; tm++) {
        int rbase = b0 + wm * 32 + tm * 16 + gr;
#pragma unroll
        for (int tn = 0; tn < 4; tn++) {
            float c0 = acc[tm][tn][0], c1 = acc[tm][tn][1];
            float c2 = acc[tm][tn][2], c3 = acc[tm][tn][3];
            float e0 = __shfl_xor_sync(0xffffffffu, c0, 1);
            float e1 = __shfl_xor_sync(0xffffffffu, c1, 1);
            float e2 = __shfl_xor_sync(0xffffffffu, c2, 1);
            float e3 = __shfl_xor_sync(0xffffffffu, c3, 1);
            float iv, fv, ov, gv;
            int brow;
            if ((q & 1) == 0) { iv = c0; fv = c1; ov = e0; gv = e1; brow = rbase; }
            else              { iv = e2; fv = e3; ov = c2; gv = c3; brow = rbase + 8; }
            int jj4 = wn * 32 + tn * 8 + (q >> 1) * 4;
            const __half* bsp = &bsum2[(brow - b0) * 128 + jj4];
            float gi = sigmf(iv + __half2float(bsp[0]));
            float gf = sigmf(fv + __half2float(bsp[1]));
            float go = sigmf(ov + __half2float(bsp[2]));
            float gg = tanhf(gv + __half2float(bsp[3]));
            int jg = j0 + (jj4 >> 2);
            int kp = (jg & ~31) + k2slot(jg & 31);   // store h perm32'd
            size_t ci = (size_t)brow * HN + jg;
            float cn = gf * cst[ci] + gi * gg;
            cst[ci] = cn;
            hout[(size_t)brow * HN + kp] = __float2half_rn(go * tanhf(cn));
        }
    }
}

// ============================================================================
// fc_kernel: y[b,s,v] = [hf(s)|hb(s)] . Wfc[v,:] + bfc[v]. K=1024 fp16,
// 32 chunks of 32. CTA 128 rows x 128 cols, 512 threads = 16 warps (4m x 4n),
// warp tile 32x32 (tm=2 m16 tiles). A via smem (perm32 h), B direct LDG.
// ============================================================================
__global__ __launch_bounds__(512, 1) void fc_kernel(const float* __restrict__ bfc,
                                                    float* __restrict__ y) {
    __shared__ __align__(16) __half As[2][2][128 * 32];
    __shared__ float bsh[128];

    const int tid = threadIdx.x;
    const int s = blockIdx.x >> 2;
    const int b0r = (blockIdx.x & 3) * 128;

    const __half* Af = g_hs_f + (size_t)(s + 1) * BN * HN;
    const __half* Ab = g_hs_b + (size_t)(SN - s) * BN * HN;

    if (tid < 128) bsh[tid] = bfc[tid];

    const int lrow = tid >> 2, lseg = tid & 3;       // 8 halfs/thread/chunk
    const int w = tid >> 5, lane = tid & 31;
    const int wm = w >> 2, wn = w & 3;               // 4x4 warp grid, warp tile 32x32
    const int gr = lane >> 2, q = lane & 3;
    const int swz = (gr >> 1) & 3;
    const int stsOff = lrow * 32 + 8 * (lseg ^ ((lrow >> 1) & 3));
    const int aOffBase = wm * 1024 + gr * 32 + 8 * (q ^ swz);   // warp covers 32 rows

    const __half* afRow = Af + (size_t)(b0r + lrow) * HN;
    const __half* abRow = Ab + (size_t)(b0r + lrow) * HN;
    const __half* bPtr = g_wfc + (size_t)(wn * 32 + gr) * 1024 + q * 8;

    float acc[2][4][4];
#pragma unroll
    for (int i = 0; i < 2; i++)
#pragma unroll
        for (int jx = 0; jx < 4; jx++)
#pragma unroll
            for (int kx = 0; kx < 4; kx++) acc[i][jx][kx] = 0.f;

    uint4 bF[2][4], rA0, rA1;

    auto loadAFC = [&](int ch, uint4& dst) {
        const __half* src = (ch < 16) ? (afRow + ch * 32) : (abRow + (ch - 16) * 32);
        dst = *(const uint4*)(src + lseg * 8);
    };
    auto loadBFC = [&](int ch, int buf) {
#pragma unroll
        for (int tn = 0; tn < 4; tn++)
            bF[buf][tn] = *(const uint4*)(bPtr + (size_t)tn * 8 * 1024 + ch * 32);
    };
    auto compFC = [&](const __half* S, int bb) {
#pragma unroll
        for (int tm = 0; tm < 2; tm++) {
            const __half* base = S + tm * 512 + aOffBase;
            uint4 A0 = *(const uint4*)(base);
            uint4 A1 = *(const uint4*)(base + 256);
            unsigned af0[4] = {A0.x, A1.x, A0.y, A1.y};
            unsigned af1[4] = {A0.z, A1.z, A0.w, A1.w};
#pragma unroll
            for (int tn = 0; tn < 4; tn++) {
                unsigned bk0[2] = {bF[bb][tn].x, bF[bb][tn].y};
                unsigned bk1[2] = {bF[bb][tn].z, bF[bb][tn].w};
                mma_f16(acc[tm][tn], af0, bk0);
                mma_f16(acc[tm][tn], af1, bk1);
            }
        }
    };

    loadAFC(0, rA0);
    loadAFC(1, rA1);
    loadBFC(0, 0);
    for (int kc = 0; kc < 32; kc += 2) {
        const int p = (kc >> 1) & 1;
        *(uint4*)(&As[p][0][stsOff]) = rA0;
        *(uint4*)(&As[p][1][stsOff]) = rA1;
        loadBFC(kc + 1, 1);
        if (kc + 2 < 32) { loadAFC(kc + 2, rA0); loadAFC(kc + 3, rA1); }
        __syncthreads();
        compFC(As[p][0], 0);
        if (kc + 2 < 32) loadBFC(kc + 2, 0);
        compFC(As[p][1], 1);
    }

#pragma unroll
    for (int tm = 0; tm < 2; tm++) {
        int b = b0r + wm * 32 + tm * 16 + gr;
#pragma unroll
        for (int tn = 0; tn < 4; tn++) {
            int n0 = wn * 32 + tn * 8 + 2 * q;
            float2 w0 = make_float2(acc[tm][tn][0] + bsh[n0], acc[tm][tn][1] + bsh[n0 + 1]);
            *(float2*)(y + ((size_t)b * SN + s) * VN + n0) = w0;
            float2 w1 = make_float2(acc[tm][tn][2] + bsh[n0], acc[tm][tn][3] + bsh[n0 + 1]);
            *(float2*)(y + ((size_t)(b + 8) * SN + s) * VN + n0) = w1;
        }
    }
}

extern "C" void kernel_launch(void* const* d_in, const int* in_sizes, int n_in,
                              void* d_out, int out_size) {
    const int*   x    = (const int*)d_in[0];
    const float* Wx_f = (const float*)d_in[1];
    const float* Wh_f = (const float*)d_in[2];
    const float* bx_f = (const float*)d_in[3];
    const float* bh_f = (const float*)d_in[4];
    const float* Wx_b = (const float*)d_in[5];
    const float* Wh_b = (const float*)d_in[6];
    const float* bx_b = (const float*)d_in[7];
    const float* bh_b = (const float*)d_in[8];
    const float* Wfc  = (const float*)d_in[9];
    const float* bfc  = (const float*)d_in[10];
    float* y = (float*)d_out;

    init_kernel<<<2048, 256>>>();
    pack_w_kernel<<<(2 * 2048 * 640 + 255) / 256, 256>>>(Wh_f, Wx_f, Wh_b, Wx_b);
    pack_wfc_kernel<<<(VN * 1024 + 255) / 256, 256>>>(Wfc);
    pack_wxp_kernel<<<(2 * VN * 2048 + 255) / 256, 256>>>(Wx_f, bx_f, bh_f, Wx_b, bx_b, bh_b);

    // 256 sequential recurrence steps; both directions fused per launch.
    dim3 g(8, 16, 2);  // 8 batch tiles x 16 neuron tiles x 2 directions = 256 CTAs (2/SM)
    for (int t = 0; t < SN; t++)
        step_kernel<<<g, 256>>>(t, x);

    // final projection over all (s, b): 256 s x 4 batch tiles
    fc_kernel<<<1024, 512>>>(bfc, y);
}